// round 4
// baseline (speedup 1.0000x reference)
#include <cuda_runtime.h>
#include <cuda_bf16.h>
#include <math.h>
#include <stdint.h>

// Problem constants
#define B_    32
#define S_    256
#define EH_   768
#define DH_   128
#define E_    200
#define V_    32000
#define T_    96
#define NS_   95            // decode steps
#define KX_   1096          // X columns: h(128) | weighted(768) | emb(200)
#define MX_   (NS_ * B_)    // 3040 rows of X

// ---------------- scratch (static __device__, no runtime alloc) ---------------
__device__ float g_encProj[B_ * S_ * DH_];     // enc @ attn_W[128:,:] + attn_b   (4.2 MB)
__device__ float g_scores[B_ * S_];            // per-step attention logits
__device__ float g_gates[B_ * 4 * DH_];        // per-step raw LSTM gates (i,f,g,o)
__device__ float g_c[2][B_ * DH_];             // cell state ping-pong
__device__ float g_X[MX_ * KX_];               // fc GEMM LHS                     (13.3 MB)

// ---------------- math helpers ----------------
__device__ __forceinline__ float tanh_acc(float x) {
    // accurate-enough tanh: (1 - e^{-2|x|}) / (1 + e^{-2|x|}), no overflow
    float ax = fabsf(x);
    float t  = __expf(-2.0f * ax);              // in (0,1]
    float r  = __fdividef(1.0f - t, 1.0f + t);
    return (x < 0.0f) ? -r : r;
}
__device__ __forceinline__ float sigm(float x) {
    return __fdividef(1.0f, 1.0f + __expf(-x));
}

// ---------------- kernel: zero outputs[:, 0, :] ----------------
__global__ void k_zero_t0(float* __restrict__ out) {
    int b = blockIdx.x;
    size_t base = (size_t)(b * T_) * V_;
    for (int v = threadIdx.x; v < V_; v += blockDim.x) out[base + v] = 0.0f;
}

// ---------------- kernel: gather embeddings into X[:, 896:1096] ----------------
__global__ void k_embed(const int* __restrict__ trg, const float* __restrict__ emb) {
    int k = blockIdx.x;   // step 0..94
    int b = blockIdx.y;   // batch
    int tid = threadIdx.x;
    if (tid < E_) {
        int tok = trg[b * T_ + k];                  // trg[:, k]
        g_X[(size_t)(k * B_ + b) * KX_ + (DH_ + EH_) + tid] = emb[(size_t)tok * E_ + tid];
    }
}

// ---------------- kernel: encProj = enc @ attn_W[128:,:] + attn_b ----------------
// M = B*S = 8192, N = 128, K = 768. Tile 64x128, BK=16, 256 threads, 8x4 micro.
__global__ void k_encproj(const float* __restrict__ enc,
                          const float* __restrict__ attn_W,
                          const float* __restrict__ attn_b) {
    __shared__ float As[64 * 16];
    __shared__ float Ws[16 * 128];
    int r0  = blockIdx.x * 64;
    int tid = threadIdx.x;
    int cx  = tid & 31;        // col group: cols cx*4 .. +3
    int ry  = tid >> 5;        // row group: rows ry*8 .. +7
    float acc[8][4];
#pragma unroll
    for (int i = 0; i < 8; i++)
#pragma unroll
        for (int j = 0; j < 4; j++) acc[i][j] = 0.0f;

    for (int k0 = 0; k0 < EH_; k0 += 16) {
        // load A tile [64 x 16]
        {
            int row = tid >> 2;
            int kk  = (tid & 3) * 4;
            float4 a = *reinterpret_cast<const float4*>(
                &enc[(size_t)(r0 + row) * EH_ + k0 + kk]);
            As[row * 16 + kk + 0] = a.x; As[row * 16 + kk + 1] = a.y;
            As[row * 16 + kk + 2] = a.z; As[row * 16 + kk + 3] = a.w;
        }
        // load W tile [16 x 128] (rows 128+k of attn_W)
        {
            int kk = tid >> 4;
            int j  = (tid & 15) * 8;
            float4 w0 = *reinterpret_cast<const float4*>(&attn_W[(size_t)(128 + k0 + kk) * 128 + j]);
            float4 w1 = *reinterpret_cast<const float4*>(&attn_W[(size_t)(128 + k0 + kk) * 128 + j + 4]);
            *reinterpret_cast<float4*>(&Ws[kk * 128 + j])     = w0;
            *reinterpret_cast<float4*>(&Ws[kk * 128 + j + 4]) = w1;
        }
        __syncthreads();
#pragma unroll
        for (int kk = 0; kk < 16; kk++) {
            float4 w = *reinterpret_cast<const float4*>(&Ws[kk * 128 + cx * 4]);
#pragma unroll
            for (int i = 0; i < 8; i++) {
                float a = As[(ry * 8 + i) * 16 + kk];
                acc[i][0] = fmaf(a, w.x, acc[i][0]);
                acc[i][1] = fmaf(a, w.y, acc[i][1]);
                acc[i][2] = fmaf(a, w.z, acc[i][2]);
                acc[i][3] = fmaf(a, w.w, acc[i][3]);
            }
        }
        __syncthreads();
    }
    float4 bias = *reinterpret_cast<const float4*>(&attn_b[cx * 4]);
#pragma unroll
    for (int i = 0; i < 8; i++) {
        int r = r0 + ry * 8 + i;
        float4 o;
        o.x = acc[i][0] + bias.x; o.y = acc[i][1] + bias.y;
        o.z = acc[i][2] + bias.z; o.w = acc[i][3] + bias.w;
        *reinterpret_cast<float4*>(&g_encProj[(size_t)r * 128 + cx * 4]) = o;
    }
}

// ---------------- per-step kernel A: cell update (for h_k) + attention scores ----
// grid = 256 blocks: b = blockIdx>>3, s-chunk = blockIdx&7 ; 128 threads
__global__ void k_attn(int k, const float* __restrict__ attn_W,
                       const float* __restrict__ attn_v) {
    int b   = blockIdx.x >> 3;
    int ch  = blockIdx.x & 7;
    int tid = threadIdx.x;
    __shared__ float sh_h[DH_];
    __shared__ float sh_w[DH_];

    if (k > 0) {
        int d = tid;
        float gi = g_gates[b * 512 + d];
        float gf = g_gates[b * 512 + 128 + d];
        float gg = g_gates[b * 512 + 256 + d];
        float go = g_gates[b * 512 + 384 + d];
        float cp = (k == 1) ? 0.0f : g_c[(k - 1) & 1][b * 128 + d];
        float cn = sigm(gf) * cp + sigm(gi) * tanh_acc(gg);
        float h  = sigm(go) * tanh_acc(cn);
        g_c[k & 1][b * 128 + d] = cn;                       // redundant across 8 blocks: same value
        g_X[(size_t)((k - 1) * B_ + b) * KX_ + d] = h;      // h_k is used in pred_{k-1}
        sh_h[d] = h;
    } else {
        sh_h[tid] = 0.0f;
    }
    __syncthreads();

    // hW[j] = sum_d h[d] * attn_W[d][j]   (rows 0..127 of attn_W)
    {
        float acc = 0.0f;
#pragma unroll 8
        for (int d = 0; d < 128; d++) acc = fmaf(sh_h[d], attn_W[d * 128 + tid], acc);
        sh_w[tid] = acc;
    }
    __syncthreads();

    // scores for 32 s-positions, 4 threads per s
    int sub = tid & 3;
    int s   = ch * 32 + (tid >> 2);
    const float* ep = g_encProj + (size_t)(b * S_ + s) * 128 + sub * 32;
    const float* hw = sh_w + sub * 32;
    const float* vv = attn_v + sub * 32;
    float acc = 0.0f;
#pragma unroll
    for (int j = 0; j < 32; j++) acc = fmaf(vv[j], tanh_acc(ep[j] + hw[j]), acc);
    acc += __shfl_xor_sync(0xffffffffu, acc, 1);
    acc += __shfl_xor_sync(0xffffffffu, acc, 2);
    if (sub == 0) g_scores[b * S_ + s] = acc;
}

// ---------------- per-step kernel B: softmax + weighted + LSTM gates --------------
// grid = 32 blocks (one per batch), 256 threads
__global__ void k_swg(int k, const float* __restrict__ enc,
                      const float* __restrict__ W_ih, const float* __restrict__ W_hh,
                      const float* __restrict__ b_ih, const float* __restrict__ b_hh) {
    int b   = blockIdx.x;
    int tid = threadIdx.x;
    __shared__ float sa[S_];
    __shared__ float red[256];
    __shared__ __align__(16) float sx[E_ + EH_];   // [emb(200) | weighted(768)]
    __shared__ __align__(16) float sh[DH_];

    int m = k * B_ + b;
    // stage emb and h_k while doing softmax
    if (tid < E_)  sx[tid] = g_X[(size_t)m * KX_ + (DH_ + EH_) + tid];
    if (tid < DH_) sh[tid] = (k == 0) ? 0.0f : g_X[(size_t)((k - 1) * B_ + b) * KX_ + tid];

    float sc = g_scores[b * S_ + tid];
    red[tid] = sc; __syncthreads();
    for (int off = 128; off > 0; off >>= 1) {
        if (tid < off) red[tid] = fmaxf(red[tid], red[tid + off]);
        __syncthreads();
    }
    float mx = red[0]; __syncthreads();
    float e = __expf(sc - mx);
    red[tid] = e; __syncthreads();
    for (int off = 128; off > 0; off >>= 1) {
        if (tid < off) red[tid] += red[tid + off];
        __syncthreads();
    }
    float inv = __fdividef(1.0f, red[0]);
    sa[tid] = e * inv;
    __syncthreads();

    // weighted[d] = sum_s a[s] * enc[b,s,d]  -> sx[200+d] and g_X
    {
        const float* encb = enc + (size_t)b * S_ * EH_;
        float w0 = 0.f, w1 = 0.f, w2 = 0.f;
        for (int s = 0; s < S_; s++) {
            float a = sa[s];
            const float* row = encb + (size_t)s * EH_;
            w0 = fmaf(a, row[tid],        w0);
            w1 = fmaf(a, row[tid + 256],  w1);
            w2 = fmaf(a, row[tid + 512],  w2);
        }
        sx[E_ + tid]       = w0;
        sx[E_ + 256 + tid] = w1;
        sx[E_ + 512 + tid] = w2;
        g_X[(size_t)m * KX_ + 128 + tid]       = w0;
        g_X[(size_t)m * KX_ + 128 + 256 + tid] = w1;
        g_X[(size_t)m * KX_ + 128 + 512 + tid] = w2;
    }
    __syncthreads();

    // gates[j] = x(968) . W_ih[j] + h . W_hh[j] + b_ih[j] + b_hh[j]
    const float4* x4  = reinterpret_cast<const float4*>(sx);
    const float4* sh4 = reinterpret_cast<const float4*>(sh);
#pragma unroll
    for (int jj = 0; jj < 2; jj++) {
        int j = tid + jj * 256;
        const float4* w4 = reinterpret_cast<const float4*>(W_ih + (size_t)j * 968);
        float acc = 0.0f;
#pragma unroll 4
        for (int q = 0; q < 242; q++) {
            float4 w = w4[q], x = x4[q];
            acc = fmaf(w.x, x.x, acc); acc = fmaf(w.y, x.y, acc);
            acc = fmaf(w.z, x.z, acc); acc = fmaf(w.w, x.w, acc);
        }
        const float4* h4 = reinterpret_cast<const float4*>(W_hh + (size_t)j * 128);
#pragma unroll
        for (int q = 0; q < 32; q++) {
            float4 w = h4[q], x = sh4[q];
            acc = fmaf(w.x, x.x, acc); acc = fmaf(w.y, x.y, acc);
            acc = fmaf(w.z, x.z, acc); acc = fmaf(w.w, x.w, acc);
        }
        g_gates[b * 512 + j] = acc + b_ih[j] + b_hh[j];
    }
}

// ---------------- final cell update: h_95 into X row of step 94 ----------------
__global__ void k_final_cell() {
    int b = blockIdx.x, d = threadIdx.x;   // 32 blocks, 128 threads
    float gi = g_gates[b * 512 + d];
    float gf = g_gates[b * 512 + 128 + d];
    float gg = g_gates[b * 512 + 256 + d];
    float go = g_gates[b * 512 + 384 + d];
    float cp = g_c[0][b * 128 + d];        // c_94 lives at parity (95-1)&1 = 0
    float cn = sigm(gf) * cp + sigm(gi) * tanh_acc(gg);
    float h  = sigm(go) * tanh_acc(cn);
    g_X[(size_t)(94 * B_ + b) * KX_ + d] = h;
}

// ---------------- fc GEMM: out[m][n] = X[m] . fc_W[n] + fc_b[n] -------------------
// M=3040, N=32000, K=1096. BM=BN=128, BK=8, 256 thr, 8x8 micro, reg prefetch.
#define BM 128
#define BN 128
#define BK 8
__global__ void k_fc_gemm(const float* __restrict__ fcW, const float* __restrict__ fcb,
                          float* __restrict__ out) {
    __shared__ __align__(16) float As[BK * BM];
    __shared__ __align__(16) float Bs[BK * BN];
    int m0  = blockIdx.x * BM;
    int n0  = blockIdx.y * BN;
    int tid = threadIdx.x;
    int tx  = tid & 15;       // n micro: cols tx*8..+7
    int ty  = tid >> 4;       // m micro: rows ty*8..+7
    int ldrow = tid >> 1;     // 0..127
    int ldk   = (tid & 1) * 4;

    float acc[8][8];
#pragma unroll
    for (int i = 0; i < 8; i++)
#pragma unroll
        for (int j = 0; j < 8; j++) acc[i][j] = 0.0f;

    const int NT = KX_ / BK;  // 137
    int am = m0 + ldrow;
    float4 ra = make_float4(0.f, 0.f, 0.f, 0.f), rb;
    if (am < MX_) ra = *reinterpret_cast<const float4*>(&g_X[(size_t)am * KX_ + ldk]);
    rb = *reinterpret_cast<const float4*>(&fcW[(size_t)(n0 + ldrow) * KX_ + ldk]);

    for (int kt = 0; kt < NT; kt++) {
        As[(ldk + 0) * BM + ldrow] = ra.x;
        As[(ldk + 1) * BM + ldrow] = ra.y;
        As[(ldk + 2) * BM + ldrow] = ra.z;
        As[(ldk + 3) * BM + ldrow] = ra.w;
        Bs[(ldk + 0) * BN + ldrow] = rb.x;
        Bs[(ldk + 1) * BN + ldrow] = rb.y;
        Bs[(ldk + 2) * BN + ldrow] = rb.z;
        Bs[(ldk + 3) * BN + ldrow] = rb.w;
        __syncthreads();

        if (kt + 1 < NT) {
            int k0 = (kt + 1) * BK + ldk;
            if (am < MX_) ra = *reinterpret_cast<const float4*>(&g_X[(size_t)am * KX_ + k0]);
            rb = *reinterpret_cast<const float4*>(&fcW[(size_t)(n0 + ldrow) * KX_ + k0]);
        }

#pragma unroll
        for (int kk = 0; kk < BK; kk++) {
            float4 a0 = *reinterpret_cast<const float4*>(&As[kk * BM + ty * 8]);
            float4 a1 = *reinterpret_cast<const float4*>(&As[kk * BM + ty * 8 + 4]);
            float4 b0 = *reinterpret_cast<const float4*>(&Bs[kk * BN + tx * 8]);
            float4 b1 = *reinterpret_cast<const float4*>(&Bs[kk * BN + tx * 8 + 4]);
            float av[8] = {a0.x, a0.y, a0.z, a0.w, a1.x, a1.y, a1.z, a1.w};
            float bv[8] = {b0.x, b0.y, b0.z, b0.w, b1.x, b1.y, b1.z, b1.w};
#pragma unroll
            for (int i = 0; i < 8; i++)
#pragma unroll
                for (int j = 0; j < 8; j++) acc[i][j] = fmaf(av[i], bv[j], acc[i][j]);
        }
        __syncthreads();
    }

    // epilogue: scatter to outputs[b, kstep+1, :] with bias
    float bias[8];
#pragma unroll
    for (int j = 0; j < 8; j++) bias[j] = fcb[n0 + tx * 8 + j];
#pragma unroll
    for (int i = 0; i < 8; i++) {
        int m = m0 + ty * 8 + i;
        if (m >= MX_) continue;
        int kstep = m >> 5;
        int b     = m & 31;
        size_t base = (size_t)(b * T_ + kstep + 1) * V_ + n0 + tx * 8;
        float4 o0, o1;
        o0.x = acc[i][0] + bias[0]; o0.y = acc[i][1] + bias[1];
        o0.z = acc[i][2] + bias[2]; o0.w = acc[i][3] + bias[3];
        o1.x = acc[i][4] + bias[4]; o1.y = acc[i][5] + bias[5];
        o1.z = acc[i][6] + bias[6]; o1.w = acc[i][7] + bias[7];
        *reinterpret_cast<float4*>(&out[base])     = o0;
        *reinterpret_cast<float4*>(&out[base + 4]) = o1;
    }
}

// ---------------- argmax over V per (b,t) row, first-occurrence ties ----------------
__global__ void k_argmax(const float* __restrict__ out, float* __restrict__ tok) {
    int r = blockIdx.x;                      // r = b*96 + t
    const float* row = out + (size_t)r * V_;
    int tid = threadIdx.x;
    float best = -__int_as_float(0x7f800000); // -inf
    int   bi   = 0;
    for (int v = tid; v < V_; v += 256) {
        float f = row[v];
        if (f > best) { best = f; bi = v; }
    }
    __shared__ float bv[256];
    __shared__ int   bid[256];
    bv[tid] = best; bid[tid] = bi; __syncthreads();
    for (int off = 128; off > 0; off >>= 1) {
        if (tid < off) {
            if (bv[tid + off] > bv[tid] ||
                (bv[tid + off] == bv[tid] && bid[tid + off] < bid[tid])) {
                bv[tid] = bv[tid + off]; bid[tid] = bid[tid + off];
            }
        }
        __syncthreads();
    }
    if (tid == 0) tok[r] = (float)bid[0];
}

// ---------------- launch ----------------
extern "C" void kernel_launch(void* const* d_in, const int* in_sizes, int n_in,
                              void* d_out, int out_size) {
    const float* enc    = (const float*)d_in[0];
    const int*   trg    = (const int*)  d_in[1];
    const float* emb    = (const float*)d_in[2];
    const float* attn_W = (const float*)d_in[3];
    const float* attn_b = (const float*)d_in[4];
    const float* attn_v = (const float*)d_in[5];
    const float* W_ih   = (const float*)d_in[6];
    const float* W_hh   = (const float*)d_in[7];
    const float* b_ih   = (const float*)d_in[8];
    const float* b_hh   = (const float*)d_in[9];
    const float* fc_W   = (const float*)d_in[10];
    const float* fc_b   = (const float*)d_in[11];
    float* out = (float*)d_out;

    k_zero_t0<<<B_, 256>>>(out);
    k_embed<<<dim3(NS_, B_), 256>>>(trg, emb);
    k_encproj<<<(B_ * S_) / 64, 256>>>(enc, attn_W, attn_b);

    for (int k = 0; k < NS_; k++) {
        k_attn<<<B_ * 8, 128>>>(k, attn_W, attn_v);
        k_swg<<<B_, 256>>>(k, enc, W_ih, W_hh, b_ih, b_hh);
    }
    k_final_cell<<<B_, 128>>>();

    k_fc_gemm<<<dim3((MX_ + BM - 1) / BM, V_ / BN), 256>>>(fc_W, fc_b, out);

    const long long btv = (long long)B_ * T_ * V_;
    if ((long long)out_size >= btv + (long long)B_ * T_) {
        k_argmax<<<B_ * T_, 256>>>(out, out + btv);
    }
}

// round 5
// speedup vs baseline: 1.0018x; 1.0018x over previous
#include <cuda_runtime.h>
#include <cuda_bf16.h>
#include <math.h>
#include <stdint.h>

// Problem constants
#define B_    32
#define S_    256
#define EH_   768
#define DH_   128
#define E_    200
#define V_    32000
#define T_    96
#define NS_   95            // decode steps
#define KX_   1096          // X columns: h(128) | weighted(768) | emb(200)
#define MX_   (NS_ * B_)    // 3040 rows of X

// ---------------- scratch (static __device__, no runtime alloc) ---------------
__device__ float g_encProj[B_ * S_ * DH_];     // enc @ attn_W[128:,:] + attn_b   (4.2 MB)
__device__ float g_scores[B_ * S_];            // per-step attention logits
__device__ float g_gates[B_ * 4 * DH_];        // per-step raw LSTM gates (i,f,g,o)
__device__ float g_c[2][B_ * DH_];             // cell state ping-pong
__device__ float g_X[MX_ * KX_];               // fc GEMM LHS                     (13.3 MB)

// ---------------- math helpers ----------------
__device__ __forceinline__ float tanh_acc(float x) {
    // accurate-enough tanh: (1 - e^{-2|x|}) / (1 + e^{-2|x|}), no overflow
    float ax = fabsf(x);
    float t  = __expf(-2.0f * ax);              // in (0,1]
    float r  = __fdividef(1.0f - t, 1.0f + t);
    return (x < 0.0f) ? -r : r;
}
__device__ __forceinline__ float sigm(float x) {
    return __fdividef(1.0f, 1.0f + __expf(-x));
}

// ---------------- kernel: zero outputs[:, 0, :] ----------------
__global__ void k_zero_t0(float* __restrict__ out) {
    int b = blockIdx.x;
    size_t base = (size_t)(b * T_) * V_;
    for (int v = threadIdx.x; v < V_; v += blockDim.x) out[base + v] = 0.0f;
}

// ---------------- kernel: gather embeddings into X[:, 896:1096] ----------------
__global__ void k_embed(const int* __restrict__ trg, const float* __restrict__ emb) {
    int k = blockIdx.x;   // step 0..94
    int b = blockIdx.y;   // batch
    int tid = threadIdx.x;
    if (tid < E_) {
        int tok = trg[b * T_ + k];                  // trg[:, k]
        g_X[(size_t)(k * B_ + b) * KX_ + (DH_ + EH_) + tid] = emb[(size_t)tok * E_ + tid];
    }
}

// ---------------- kernel: encProj = enc @ attn_W[128:,:] + attn_b ----------------
// M = B*S = 8192, N = 128, K = 768. Tile 64x128, BK=16, 256 threads, 8x4 micro.
__global__ void k_encproj(const float* __restrict__ enc,
                          const float* __restrict__ attn_W,
                          const float* __restrict__ attn_b) {
    __shared__ float As[64 * 16];
    __shared__ float Ws[16 * 128];
    int r0  = blockIdx.x * 64;
    int tid = threadIdx.x;
    int cx  = tid & 31;        // col group: cols cx*4 .. +3
    int ry  = tid >> 5;        // row group: rows ry*8 .. +7
    float acc[8][4];
#pragma unroll
    for (int i = 0; i < 8; i++)
#pragma unroll
        for (int j = 0; j < 4; j++) acc[i][j] = 0.0f;

    for (int k0 = 0; k0 < EH_; k0 += 16) {
        // load A tile [64 x 16]
        {
            int row = tid >> 2;
            int kk  = (tid & 3) * 4;
            float4 a = *reinterpret_cast<const float4*>(
                &enc[(size_t)(r0 + row) * EH_ + k0 + kk]);
            As[row * 16 + kk + 0] = a.x; As[row * 16 + kk + 1] = a.y;
            As[row * 16 + kk + 2] = a.z; As[row * 16 + kk + 3] = a.w;
        }
        // load W tile [16 x 128] (rows 128+k of attn_W)
        {
            int kk = tid >> 4;
            int j  = (tid & 15) * 8;
            float4 w0 = *reinterpret_cast<const float4*>(&attn_W[(size_t)(128 + k0 + kk) * 128 + j]);
            float4 w1 = *reinterpret_cast<const float4*>(&attn_W[(size_t)(128 + k0 + kk) * 128 + j + 4]);
            *reinterpret_cast<float4*>(&Ws[kk * 128 + j])     = w0;
            *reinterpret_cast<float4*>(&Ws[kk * 128 + j + 4]) = w1;
        }
        __syncthreads();
#pragma unroll
        for (int kk = 0; kk < 16; kk++) {
            float4 w = *reinterpret_cast<const float4*>(&Ws[kk * 128 + cx * 4]);
#pragma unroll
            for (int i = 0; i < 8; i++) {
                float a = As[(ry * 8 + i) * 16 + kk];
                acc[i][0] = fmaf(a, w.x, acc[i][0]);
                acc[i][1] = fmaf(a, w.y, acc[i][1]);
                acc[i][2] = fmaf(a, w.z, acc[i][2]);
                acc[i][3] = fmaf(a, w.w, acc[i][3]);
            }
        }
        __syncthreads();
    }
    float4 bias = *reinterpret_cast<const float4*>(&attn_b[cx * 4]);
#pragma unroll
    for (int i = 0; i < 8; i++) {
        int r = r0 + ry * 8 + i;
        float4 o;
        o.x = acc[i][0] + bias.x; o.y = acc[i][1] + bias.y;
        o.z = acc[i][2] + bias.z; o.w = acc[i][3] + bias.w;
        *reinterpret_cast<float4*>(&g_encProj[(size_t)r * 128 + cx * 4]) = o;
    }
}

// ---------------- per-step kernel A: cell update (for h_k) + attention scores ----
// grid = 256 blocks: b = blockIdx>>3, s-chunk = blockIdx&7 ; 128 threads
__global__ void k_attn(int k, const float* __restrict__ attn_W,
                       const float* __restrict__ attn_v) {
    int b   = blockIdx.x >> 3;
    int ch  = blockIdx.x & 7;
    int tid = threadIdx.x;
    __shared__ float sh_h[DH_];
    __shared__ float sh_w[DH_];

    if (k > 0) {
        int d = tid;
        float gi = g_gates[b * 512 + d];
        float gf = g_gates[b * 512 + 128 + d];
        float gg = g_gates[b * 512 + 256 + d];
        float go = g_gates[b * 512 + 384 + d];
        float cp = (k == 1) ? 0.0f : g_c[(k - 1) & 1][b * 128 + d];
        float cn = sigm(gf) * cp + sigm(gi) * tanh_acc(gg);
        float h  = sigm(go) * tanh_acc(cn);
        g_c[k & 1][b * 128 + d] = cn;                       // redundant across 8 blocks: same value
        g_X[(size_t)((k - 1) * B_ + b) * KX_ + d] = h;      // h_k is used in pred_{k-1}
        sh_h[d] = h;
    } else {
        sh_h[tid] = 0.0f;
    }
    __syncthreads();

    // hW[j] = sum_d h[d] * attn_W[d][j]   (rows 0..127 of attn_W)
    {
        float acc = 0.0f;
#pragma unroll 8
        for (int d = 0; d < 128; d++) acc = fmaf(sh_h[d], attn_W[d * 128 + tid], acc);
        sh_w[tid] = acc;
    }
    __syncthreads();

    // scores for 32 s-positions, 4 threads per s
    int sub = tid & 3;
    int s   = ch * 32 + (tid >> 2);
    const float* ep = g_encProj + (size_t)(b * S_ + s) * 128 + sub * 32;
    const float* hw = sh_w + sub * 32;
    const float* vv = attn_v + sub * 32;
    float acc = 0.0f;
#pragma unroll
    for (int j = 0; j < 32; j++) acc = fmaf(vv[j], tanh_acc(ep[j] + hw[j]), acc);
    acc += __shfl_xor_sync(0xffffffffu, acc, 1);
    acc += __shfl_xor_sync(0xffffffffu, acc, 2);
    if (sub == 0) g_scores[b * S_ + s] = acc;
}

// ---------------- per-step kernel B: softmax + weighted + LSTM gates --------------
// grid = 32 blocks (one per batch), 256 threads
__global__ void k_swg(int k, const float* __restrict__ enc,
                      const float* __restrict__ W_ih, const float* __restrict__ W_hh,
                      const float* __restrict__ b_ih, const float* __restrict__ b_hh) {
    int b   = blockIdx.x;
    int tid = threadIdx.x;
    __shared__ float sa[S_];
    __shared__ float red[256];
    __shared__ __align__(16) float sx[E_ + EH_];   // [emb(200) | weighted(768)]
    __shared__ __align__(16) float sh[DH_];

    int m = k * B_ + b;
    // stage emb and h_k while doing softmax
    if (tid < E_)  sx[tid] = g_X[(size_t)m * KX_ + (DH_ + EH_) + tid];
    if (tid < DH_) sh[tid] = (k == 0) ? 0.0f : g_X[(size_t)((k - 1) * B_ + b) * KX_ + tid];

    float sc = g_scores[b * S_ + tid];
    red[tid] = sc; __syncthreads();
    for (int off = 128; off > 0; off >>= 1) {
        if (tid < off) red[tid] = fmaxf(red[tid], red[tid + off]);
        __syncthreads();
    }
    float mx = red[0]; __syncthreads();
    float e = __expf(sc - mx);
    red[tid] = e; __syncthreads();
    for (int off = 128; off > 0; off >>= 1) {
        if (tid < off) red[tid] += red[tid + off];
        __syncthreads();
    }
    float inv = __fdividef(1.0f, red[0]);
    sa[tid] = e * inv;
    __syncthreads();

    // weighted[d] = sum_s a[s] * enc[b,s,d]  -> sx[200+d] and g_X
    {
        const float* encb = enc + (size_t)b * S_ * EH_;
        float w0 = 0.f, w1 = 0.f, w2 = 0.f;
        for (int s = 0; s < S_; s++) {
            float a = sa[s];
            const float* row = encb + (size_t)s * EH_;
            w0 = fmaf(a, row[tid],        w0);
            w1 = fmaf(a, row[tid + 256],  w1);
            w2 = fmaf(a, row[tid + 512],  w2);
        }
        sx[E_ + tid]       = w0;
        sx[E_ + 256 + tid] = w1;
        sx[E_ + 512 + tid] = w2;
        g_X[(size_t)m * KX_ + 128 + tid]       = w0;
        g_X[(size_t)m * KX_ + 128 + 256 + tid] = w1;
        g_X[(size_t)m * KX_ + 128 + 512 + tid] = w2;
    }
    __syncthreads();

    // gates[j] = x(968) . W_ih[j] + h . W_hh[j] + b_ih[j] + b_hh[j]
    const float4* x4  = reinterpret_cast<const float4*>(sx);
    const float4* sh4 = reinterpret_cast<const float4*>(sh);
#pragma unroll
    for (int jj = 0; jj < 2; jj++) {
        int j = tid + jj * 256;
        const float4* w4 = reinterpret_cast<const float4*>(W_ih + (size_t)j * 968);
        float acc = 0.0f;
#pragma unroll 4
        for (int q = 0; q < 242; q++) {
            float4 w = w4[q], x = x4[q];
            acc = fmaf(w.x, x.x, acc); acc = fmaf(w.y, x.y, acc);
            acc = fmaf(w.z, x.z, acc); acc = fmaf(w.w, x.w, acc);
        }
        const float4* h4 = reinterpret_cast<const float4*>(W_hh + (size_t)j * 128);
#pragma unroll
        for (int q = 0; q < 32; q++) {
            float4 w = h4[q], x = sh4[q];
            acc = fmaf(w.x, x.x, acc); acc = fmaf(w.y, x.y, acc);
            acc = fmaf(w.z, x.z, acc); acc = fmaf(w.w, x.w, acc);
        }
        g_gates[b * 512 + j] = acc + b_ih[j] + b_hh[j];
    }
}

// ---------------- final cell update: h_95 into X row of step 94 ----------------
__global__ void k_final_cell() {
    int b = blockIdx.x, d = threadIdx.x;   // 32 blocks, 128 threads
    float gi = g_gates[b * 512 + d];
    float gf = g_gates[b * 512 + 128 + d];
    float gg = g_gates[b * 512 + 256 + d];
    float go = g_gates[b * 512 + 384 + d];
    float cp = g_c[0][b * 128 + d];        // c_94 lives at parity (95-1)&1 = 0
    float cn = sigm(gf) * cp + sigm(gi) * tanh_acc(gg);
    float h  = sigm(go) * tanh_acc(cn);
    g_X[(size_t)(94 * B_ + b) * KX_ + d] = h;
}

// ---------------- fc GEMM: out[m][n] = X[m] . fc_W[n] + fc_b[n] -------------------
// M=3040, N=32000, K=1096. BM=BN=128, BK=8, 256 thr, 8x8 micro, reg prefetch.
#define BM 128
#define BN 128
#define BK 8
__global__ void k_fc_gemm(const float* __restrict__ fcW, const float* __restrict__ fcb,
                          float* __restrict__ out) {
    __shared__ __align__(16) float As[BK * BM];
    __shared__ __align__(16) float Bs[BK * BN];
    int m0  = blockIdx.x * BM;
    int n0  = blockIdx.y * BN;
    int tid = threadIdx.x;
    int tx  = tid & 15;       // n micro: cols tx*8..+7
    int ty  = tid >> 4;       // m micro: rows ty*8..+7
    int ldrow = tid >> 1;     // 0..127
    int ldk   = (tid & 1) * 4;

    float acc[8][8];
#pragma unroll
    for (int i = 0; i < 8; i++)
#pragma unroll
        for (int j = 0; j < 8; j++) acc[i][j] = 0.0f;

    const int NT = KX_ / BK;  // 137
    int am = m0 + ldrow;
    float4 ra = make_float4(0.f, 0.f, 0.f, 0.f), rb;
    if (am < MX_) ra = *reinterpret_cast<const float4*>(&g_X[(size_t)am * KX_ + ldk]);
    rb = *reinterpret_cast<const float4*>(&fcW[(size_t)(n0 + ldrow) * KX_ + ldk]);

    for (int kt = 0; kt < NT; kt++) {
        As[(ldk + 0) * BM + ldrow] = ra.x;
        As[(ldk + 1) * BM + ldrow] = ra.y;
        As[(ldk + 2) * BM + ldrow] = ra.z;
        As[(ldk + 3) * BM + ldrow] = ra.w;
        Bs[(ldk + 0) * BN + ldrow] = rb.x;
        Bs[(ldk + 1) * BN + ldrow] = rb.y;
        Bs[(ldk + 2) * BN + ldrow] = rb.z;
        Bs[(ldk + 3) * BN + ldrow] = rb.w;
        __syncthreads();

        if (kt + 1 < NT) {
            int k0 = (kt + 1) * BK + ldk;
            if (am < MX_) ra = *reinterpret_cast<const float4*>(&g_X[(size_t)am * KX_ + k0]);
            rb = *reinterpret_cast<const float4*>(&fcW[(size_t)(n0 + ldrow) * KX_ + k0]);
        }

#pragma unroll
        for (int kk = 0; kk < BK; kk++) {
            float4 a0 = *reinterpret_cast<const float4*>(&As[kk * BM + ty * 8]);
            float4 a1 = *reinterpret_cast<const float4*>(&As[kk * BM + ty * 8 + 4]);
            float4 b0 = *reinterpret_cast<const float4*>(&Bs[kk * BN + tx * 8]);
            float4 b1 = *reinterpret_cast<const float4*>(&Bs[kk * BN + tx * 8 + 4]);
            float av[8] = {a0.x, a0.y, a0.z, a0.w, a1.x, a1.y, a1.z, a1.w};
            float bv[8] = {b0.x, b0.y, b0.z, b0.w, b1.x, b1.y, b1.z, b1.w};
#pragma unroll
            for (int i = 0; i < 8; i++)
#pragma unroll
                for (int j = 0; j < 8; j++) acc[i][j] = fmaf(av[i], bv[j], acc[i][j]);
        }
        __syncthreads();
    }

    // epilogue: scatter to outputs[b, kstep+1, :] with bias
    float bias[8];
#pragma unroll
    for (int j = 0; j < 8; j++) bias[j] = fcb[n0 + tx * 8 + j];
#pragma unroll
    for (int i = 0; i < 8; i++) {
        int m = m0 + ty * 8 + i;
        if (m >= MX_) continue;
        int kstep = m >> 5;
        int b     = m & 31;
        size_t base = (size_t)(b * T_ + kstep + 1) * V_ + n0 + tx * 8;
        float4 o0, o1;
        o0.x = acc[i][0] + bias[0]; o0.y = acc[i][1] + bias[1];
        o0.z = acc[i][2] + bias[2]; o0.w = acc[i][3] + bias[3];
        o1.x = acc[i][4] + bias[4]; o1.y = acc[i][5] + bias[5];
        o1.z = acc[i][6] + bias[6]; o1.w = acc[i][7] + bias[7];
        *reinterpret_cast<float4*>(&out[base])     = o0;
        *reinterpret_cast<float4*>(&out[base + 4]) = o1;
    }
}

// ---------------- argmax over V per (b,t) row, first-occurrence ties ----------------
__global__ void k_argmax(const float* __restrict__ out, float* __restrict__ tok) {
    int r = blockIdx.x;                      // r = b*96 + t
    const float* row = out + (size_t)r * V_;
    int tid = threadIdx.x;
    float best = -__int_as_float(0x7f800000); // -inf
    int   bi   = 0;
    for (int v = tid; v < V_; v += 256) {
        float f = row[v];
        if (f > best) { best = f; bi = v; }
    }
    __shared__ float bv[256];
    __shared__ int   bid[256];
    bv[tid] = best; bid[tid] = bi; __syncthreads();
    for (int off = 128; off > 0; off >>= 1) {
        if (tid < off) {
            if (bv[tid + off] > bv[tid] ||
                (bv[tid + off] == bv[tid] && bid[tid + off] < bid[tid])) {
                bv[tid] = bv[tid + off]; bid[tid] = bid[tid + off];
            }
        }
        __syncthreads();
    }
    if (tid == 0) tok[r] = (float)bid[0];
}

// ---------------- launch ----------------
extern "C" void kernel_launch(void* const* d_in, const int* in_sizes, int n_in,
                              void* d_out, int out_size) {
    const float* enc    = (const float*)d_in[0];
    const int*   trg    = (const int*)  d_in[1];
    const float* emb    = (const float*)d_in[2];
    const float* attn_W = (const float*)d_in[3];
    const float* attn_b = (const float*)d_in[4];
    const float* attn_v = (const float*)d_in[5];
    const float* W_ih   = (const float*)d_in[6];
    const float* W_hh   = (const float*)d_in[7];
    const float* b_ih   = (const float*)d_in[8];
    const float* b_hh   = (const float*)d_in[9];
    const float* fc_W   = (const float*)d_in[10];
    const float* fc_b   = (const float*)d_in[11];
    float* out = (float*)d_out;

    k_zero_t0<<<B_, 256>>>(out);
    k_embed<<<dim3(NS_, B_), 256>>>(trg, emb);
    k_encproj<<<(B_ * S_) / 64, 256>>>(enc, attn_W, attn_b);

    for (int k = 0; k < NS_; k++) {
        k_attn<<<B_ * 8, 128>>>(k, attn_W, attn_v);
        k_swg<<<B_, 256>>>(k, enc, W_ih, W_hh, b_ih, b_hh);
    }
    k_final_cell<<<B_, 128>>>();

    k_fc_gemm<<<dim3((MX_ + BM - 1) / BM, V_ / BN), 256>>>(fc_W, fc_b, out);

    const long long btv = (long long)B_ * T_ * V_;
    if ((long long)out_size >= btv + (long long)B_ * T_) {
        k_argmax<<<B_ * T_, 256>>>(out, out + btv);
    }
}

// round 10
// speedup vs baseline: 1.9413x; 1.9378x over previous
#include <cuda_runtime.h>
#include <cuda_bf16.h>
#include <math.h>
#include <stdint.h>

#define B_    32
#define S_    256
#define EH_   768
#define DH_   128
#define E_    200
#define V_    32000
#define T_    96
#define NS_   95
#define KX_   1096
#define MX_   (NS_ * B_)   // 3040
#define KP_   1152         // padded K (36 chunks of 32)
#define MP_   3072         // padded M
#define NT_   36           // k-chunks of 32

__device__ float g_encProj[B_ * S_ * DH_];
__device__ float g_scores[B_ * S_];
__device__ float g_gates[B_ * 4 * DH_];
__device__ float g_c[2][B_ * DH_];
__device__ float g_X[(size_t)MX_ * KX_];
__device__ __nv_bfloat16 g_Wh[(size_t)V_ * KP_];
__device__ __nv_bfloat16 g_Wl[(size_t)V_ * KP_];
__device__ __nv_bfloat16 g_Xh[(size_t)MP_ * KP_];
__device__ __nv_bfloat16 g_Xl[(size_t)MP_ * KP_];

__device__ __forceinline__ float tanh_acc(float x) {
    float ax = fabsf(x);
    float t  = __expf(-2.0f * ax);
    float r  = __fdividef(1.0f - t, 1.0f + t);
    return (x < 0.0f) ? -r : r;
}
__device__ __forceinline__ float tanh_fast(float x) {
    float y; asm("tanh.approx.f32 %0, %1;" : "=f"(y) : "f"(x)); return y;
}
__device__ __forceinline__ float sigm(float x) {
    return __fdividef(1.0f, 1.0f + __expf(-x));
}
__device__ __forceinline__ uint32_t s2u(const void* p) {
    uint32_t a;
    asm("{ .reg .u64 t; cvta.to.shared.u64 t, %1; cvt.u32.u64 %0, t; }" : "=r"(a) : "l"(p));
    return a;
}
__device__ __forceinline__ void cpa16(uint32_t dst, const void* src) {
    asm volatile("cp.async.cg.shared.global [%0], [%1], 16;" :: "r"(dst), "l"(src));
}
#define LDMX4(r, addr) \
    asm volatile("ldmatrix.sync.aligned.m8n8.x4.shared.b16 {%0,%1,%2,%3}, [%4];" \
        : "=r"((r)[0]), "=r"((r)[1]), "=r"((r)[2]), "=r"((r)[3]) : "r"(addr))
#define MMA(c, a, b0r, b1r) \
    asm volatile("mma.sync.aligned.m16n8k16.row.col.f32.bf16.bf16.f32 " \
        "{%0,%1,%2,%3}, {%4,%5,%6,%7}, {%8,%9}, {%0,%1,%2,%3};" \
        : "+f"((c)[0]), "+f"((c)[1]), "+f"((c)[2]), "+f"((c)[3]) \
        : "r"((a)[0]), "r"((a)[1]), "r"((a)[2]), "r"((a)[3]), "r"(b0r), "r"(b1r))

// ---------------- prep kernels ----------------
__global__ void k_zero_t0(float* __restrict__ out) {
    int b = blockIdx.x;
    size_t base = (size_t)(b * T_) * V_;
    for (int v = threadIdx.x; v < V_; v += blockDim.x) out[base + v] = 0.0f;
}

__global__ void k_embed(const int* __restrict__ trg, const float* __restrict__ emb) {
    int k = blockIdx.x, b = blockIdx.y, tid = threadIdx.x;
    if (tid < E_) {
        int tok = trg[b * T_ + k];
        g_X[(size_t)(k * B_ + b) * KX_ + (DH_ + EH_) + tid] = emb[(size_t)tok * E_ + tid];
    }
}

__global__ void k_cvtW(const float* __restrict__ fcW) {
    int n = blockIdx.x;
    const float* src = fcW + (size_t)n * KX_;
    __nv_bfloat162* dh = (__nv_bfloat162*)(g_Wh + (size_t)n * KP_);
    __nv_bfloat162* dl = (__nv_bfloat162*)(g_Wl + (size_t)n * KP_);
    for (int c0 = threadIdx.x * 2; c0 < KP_; c0 += 256) {
        float x0 = (c0     < KX_) ? src[c0]     : 0.0f;
        float x1 = (c0 + 1 < KX_) ? src[c0 + 1] : 0.0f;
        __nv_bfloat16 h0 = __float2bfloat16(x0), h1 = __float2bfloat16(x1);
        __nv_bfloat16 l0 = __float2bfloat16(x0 - __bfloat162float(h0));
        __nv_bfloat16 l1 = __float2bfloat16(x1 - __bfloat162float(h1));
        dh[c0 >> 1] = __nv_bfloat162(h0, h1);
        dl[c0 >> 1] = __nv_bfloat162(l0, l1);
    }
}

__global__ void k_cvtX() {
    int m = blockIdx.x;
    const float* src = g_X + (size_t)m * KX_;
    __nv_bfloat162* dh = (__nv_bfloat162*)(g_Xh + (size_t)m * KP_);
    __nv_bfloat162* dl = (__nv_bfloat162*)(g_Xl + (size_t)m * KP_);
    bool vr = (m < MX_);
    for (int c0 = threadIdx.x * 2; c0 < KP_; c0 += 256) {
        float x0 = (vr && c0     < KX_) ? src[c0]     : 0.0f;
        float x1 = (vr && c0 + 1 < KX_) ? src[c0 + 1] : 0.0f;
        __nv_bfloat16 h0 = __float2bfloat16(x0), h1 = __float2bfloat16(x1);
        __nv_bfloat16 l0 = __float2bfloat16(x0 - __bfloat162float(h0));
        __nv_bfloat16 l1 = __float2bfloat16(x1 - __bfloat162float(h1));
        dh[c0 >> 1] = __nv_bfloat162(h0, h1);
        dl[c0 >> 1] = __nv_bfloat162(l0, l1);
    }
}

// ---------------- encProj = enc @ attn_W[128:,:] + attn_b ----------------
__global__ void k_encproj(const float* __restrict__ enc,
                          const float* __restrict__ attn_W,
                          const float* __restrict__ attn_b) {
    __shared__ float As[64 * 16];
    __shared__ float Ws[16 * 128];
    int r0 = blockIdx.x * 64, tid = threadIdx.x;
    int cx = tid & 31, ry = tid >> 5;
    float acc[8][4];
#pragma unroll
    for (int i = 0; i < 8; i++)
#pragma unroll
        for (int j = 0; j < 4; j++) acc[i][j] = 0.0f;
    for (int k0 = 0; k0 < EH_; k0 += 16) {
        {
            int row = tid >> 2, kk = (tid & 3) * 4;
            float4 a = *reinterpret_cast<const float4*>(&enc[(size_t)(r0 + row) * EH_ + k0 + kk]);
            As[row * 16 + kk] = a.x; As[row * 16 + kk + 1] = a.y;
            As[row * 16 + kk + 2] = a.z; As[row * 16 + kk + 3] = a.w;
        }
        {
            int kk = tid >> 4, j = (tid & 15) * 8;
            float4 w0 = *reinterpret_cast<const float4*>(&attn_W[(size_t)(128 + k0 + kk) * 128 + j]);
            float4 w1 = *reinterpret_cast<const float4*>(&attn_W[(size_t)(128 + k0 + kk) * 128 + j + 4]);
            *reinterpret_cast<float4*>(&Ws[kk * 128 + j]) = w0;
            *reinterpret_cast<float4*>(&Ws[kk * 128 + j + 4]) = w1;
        }
        __syncthreads();
#pragma unroll
        for (int kk = 0; kk < 16; kk++) {
            float4 w = *reinterpret_cast<const float4*>(&Ws[kk * 128 + cx * 4]);
#pragma unroll
            for (int i = 0; i < 8; i++) {
                float a = As[(ry * 8 + i) * 16 + kk];
                acc[i][0] = fmaf(a, w.x, acc[i][0]); acc[i][1] = fmaf(a, w.y, acc[i][1]);
                acc[i][2] = fmaf(a, w.z, acc[i][2]); acc[i][3] = fmaf(a, w.w, acc[i][3]);
            }
        }
        __syncthreads();
    }
    float4 bias = *reinterpret_cast<const float4*>(&attn_b[cx * 4]);
#pragma unroll
    for (int i = 0; i < 8; i++) {
        int r = r0 + ry * 8 + i;
        float4 o;
        o.x = acc[i][0] + bias.x; o.y = acc[i][1] + bias.y;
        o.z = acc[i][2] + bias.z; o.w = acc[i][3] + bias.w;
        *reinterpret_cast<float4*>(&g_encProj[(size_t)r * 128 + cx * 4]) = o;
    }
}

// ---------------- step A: cell update + attention scores ----------------
__global__ void k_attn(int k, const float* __restrict__ attn_W,
                       const float* __restrict__ attn_v) {
    int b = blockIdx.x >> 3, ch = blockIdx.x & 7, tid = threadIdx.x;
    __shared__ float sh_h[DH_];
    __shared__ float sh_w[DH_];
    if (k > 0) {
        int d = tid;
        float gi = g_gates[b * 512 + d];
        float gf = g_gates[b * 512 + 128 + d];
        float gg = g_gates[b * 512 + 256 + d];
        float go = g_gates[b * 512 + 384 + d];
        float cp = (k == 1) ? 0.0f : g_c[(k - 1) & 1][b * 128 + d];
        float cn = sigm(gf) * cp + sigm(gi) * tanh_acc(gg);
        float h  = sigm(go) * tanh_acc(cn);
        g_c[k & 1][b * 128 + d] = cn;
        g_X[(size_t)((k - 1) * B_ + b) * KX_ + d] = h;
        sh_h[d] = h;
    } else sh_h[tid] = 0.0f;
    __syncthreads();
    {
        float a0 = 0.f, a1 = 0.f, a2 = 0.f, a3 = 0.f;
#pragma unroll
        for (int d = 0; d < 128; d += 4) {
            a0 = fmaf(sh_h[d],     attn_W[d * 128 + tid],       a0);
            a1 = fmaf(sh_h[d + 1], attn_W[(d + 1) * 128 + tid], a1);
            a2 = fmaf(sh_h[d + 2], attn_W[(d + 2) * 128 + tid], a2);
            a3 = fmaf(sh_h[d + 3], attn_W[(d + 3) * 128 + tid], a3);
        }
        sh_w[tid] = (a0 + a1) + (a2 + a3);
    }
    __syncthreads();
    int sub = tid & 3, s = ch * 32 + (tid >> 2);
    const float* ep = g_encProj + (size_t)(b * S_ + s) * 128 + sub * 32;
    const float* hw = sh_w + sub * 32;
    const float* vv = attn_v + sub * 32;
    float acc = 0.0f;
#pragma unroll
    for (int j = 0; j < 32; j++) acc = fmaf(vv[j], tanh_fast(ep[j] + hw[j]), acc);
    acc += __shfl_xor_sync(0xffffffffu, acc, 1);
    acc += __shfl_xor_sync(0xffffffffu, acc, 2);
    if (sub == 0) g_scores[b * S_ + s] = acc;
}

// ---------------- step B: softmax + weighted (grid 32 x 3) ----------------
__global__ void k_softw(int k, const float* __restrict__ enc) {
    int b = blockIdx.x, seg = blockIdx.y, tid = threadIdx.x;
    __shared__ float sa[S_];
    __shared__ float red[256];
    float sc = g_scores[b * S_ + tid];
    red[tid] = sc; __syncthreads();
    for (int off = 128; off > 0; off >>= 1) {
        if (tid < off) red[tid] = fmaxf(red[tid], red[tid + off]);
        __syncthreads();
    }
    float mx = red[0]; __syncthreads();
    float e = __expf(sc - mx);
    red[tid] = e; __syncthreads();
    for (int off = 128; off > 0; off >>= 1) {
        if (tid < off) red[tid] += red[tid + off];
        __syncthreads();
    }
    float inv = __fdividef(1.0f, red[0]);
    sa[tid] = e * inv;
    __syncthreads();
    int d = seg * 256 + tid;
    const float* p = enc + (size_t)b * S_ * EH_ + d;
    float w0 = 0.f, w1 = 0.f, w2 = 0.f, w3 = 0.f;
#pragma unroll 4
    for (int s = 0; s < S_; s += 4) {
        w0 = fmaf(sa[s],     p[(size_t)s * EH_],       w0);
        w1 = fmaf(sa[s + 1], p[(size_t)(s + 1) * EH_], w1);
        w2 = fmaf(sa[s + 2], p[(size_t)(s + 2) * EH_], w2);
        w3 = fmaf(sa[s + 3], p[(size_t)(s + 3) * EH_], w3);
    }
    g_X[(size_t)(k * B_ + b) * KX_ + DH_ + d] = (w0 + w1) + (w2 + w3);
}

// ---------------- step C: LSTM gates (grid 64) ----------------
#define GW 1100
__global__ void k_gates(int k, const float* __restrict__ W_ih, const float* __restrict__ W_hh,
                        const float* __restrict__ b_ih, const float* __restrict__ b_hh) {
    __shared__ __align__(16) float Ws[8 * GW];   // [W_ih row(968) | W_hh row(128)]
    int j0 = blockIdx.x * 8, tid = threadIdx.x;
    for (int i = tid; i < 8 * 242; i += 256) {
        int g = i / 242, q = i - g * 242;
        *reinterpret_cast<float4*>(&Ws[g * GW + q * 4]) =
            *reinterpret_cast<const float4*>(&W_ih[(size_t)(j0 + g) * 968 + q * 4]);
    }
    for (int i = tid; i < 8 * 32; i += 256) {
        int g = i >> 5, q = i & 31;
        *reinterpret_cast<float4*>(&Ws[g * GW + 968 + q * 4]) =
            *reinterpret_cast<const float4*>(&W_hh[(size_t)(j0 + g) * 128 + q * 4]);
    }
    __syncthreads();
    int b = tid >> 3, g = tid & 7, j = j0 + g;
    size_t m = (size_t)k * B_ + b;
    const float4* xe = reinterpret_cast<const float4*>(&g_X[m * KX_ + 896]);  // emb(200)
    const float4* xw = reinterpret_cast<const float4*>(&g_X[m * KX_ + 128]);  // weighted(768)
    const float4* we = reinterpret_cast<const float4*>(&Ws[g * GW]);
    const float4* ww = reinterpret_cast<const float4*>(&Ws[g * GW + 200]);
    float4 a4 = make_float4(0.f, 0.f, 0.f, 0.f);
#pragma unroll 5
    for (int q = 0; q < 50; q++) {
        float4 w = we[q], x = xe[q];
        a4.x = fmaf(w.x, x.x, a4.x); a4.y = fmaf(w.y, x.y, a4.y);
        a4.z = fmaf(w.z, x.z, a4.z); a4.w = fmaf(w.w, x.w, a4.w);
    }
#pragma unroll 8
    for (int q = 0; q < 192; q++) {
        float4 w = ww[q], x = xw[q];
        a4.x = fmaf(w.x, x.x, a4.x); a4.y = fmaf(w.y, x.y, a4.y);
        a4.z = fmaf(w.z, x.z, a4.z); a4.w = fmaf(w.w, x.w, a4.w);
    }
    if (k > 0) {
        const float4* xh = reinterpret_cast<const float4*>(&g_X[((size_t)(k - 1) * B_ + b) * KX_]);
        const float4* wh = reinterpret_cast<const float4*>(&Ws[g * GW + 968]);
#pragma unroll
        for (int q = 0; q < 32; q++) {
            float4 w = wh[q], x = xh[q];
            a4.x = fmaf(w.x, x.x, a4.x); a4.y = fmaf(w.y, x.y, a4.y);
            a4.z = fmaf(w.z, x.z, a4.z); a4.w = fmaf(w.w, x.w, a4.w);
        }
    }
    g_gates[b * 512 + j] = ((a4.x + a4.y) + (a4.z + a4.w)) + b_ih[j] + b_hh[j];
}

__global__ void k_final_cell() {
    int b = blockIdx.x, d = threadIdx.x;
    float gi = g_gates[b * 512 + d];
    float gf = g_gates[b * 512 + 128 + d];
    float gg = g_gates[b * 512 + 256 + d];
    float go = g_gates[b * 512 + 384 + d];
    float cp = g_c[0][b * 128 + d];
    float cn = sigm(gf) * cp + sigm(gi) * tanh_acc(gg);
    float h  = sigm(go) * tanh_acc(cn);
    g_X[(size_t)(94 * B_ + b) * KX_ + d] = h;
}

// ---------------- fc GEMM via mma.sync bf16 hi/lo 3-pass ----------------
// BM=BN=128, BK=32; 8 warps as 4(m) x 2(n), warp tile 32x64.
// SMEM stage: Ah | Al | Bh | Bl, each 128 rows x 64B payload @ 80B stride.
#define ASTRIDE 80
#define MAT_B   (128 * ASTRIDE)   // 10240
#define STG_B   (4 * MAT_B)       // 40960
__global__ void __launch_bounds__(256, 2) k_fc_mma(const float* __restrict__ fcb,
                                                   float* __restrict__ out) {
    extern __shared__ __align__(16) char smb[];
    uint32_t sb = s2u(smb);
    int tid = threadIdx.x, wid = tid >> 5, lid = tid & 31;
    int m0 = blockIdx.x * 128, n0 = blockIdx.y * 128;

    float acc[2][8][4];
#pragma unroll
    for (int i = 0; i < 2; i++)
#pragma unroll
        for (int j = 0; j < 8; j++)
#pragma unroll
            for (int q = 0; q < 4; q++) acc[i][j][q] = 0.0f;

    int lr = tid >> 2, lc = tid & 3;           // loader: row 0..63(+64), chunk 0..3
    uint32_t d0 = sb + lr * ASTRIDE + lc * 16;
    uint32_t d1 = sb + (lr + 64) * ASTRIDE + lc * 16;

#define ISSUE(kc, buf) do {                                                        \
        int kb = (kc) * 32;                                                        \
        uint32_t st0 = d0 + (buf) * STG_B, st1 = d1 + (buf) * STG_B;               \
        const __nv_bfloat16* a0p = g_Xh + (size_t)(m0 + lr) * KP_ + kb + lc * 8;   \
        const __nv_bfloat16* a1p = g_Xh + (size_t)(m0 + lr + 64) * KP_ + kb + lc * 8; \
        const __nv_bfloat16* c0p = g_Xl + (size_t)(m0 + lr) * KP_ + kb + lc * 8;   \
        const __nv_bfloat16* c1p = g_Xl + (size_t)(m0 + lr + 64) * KP_ + kb + lc * 8; \
        const __nv_bfloat16* b0p = g_Wh + (size_t)(n0 + lr) * KP_ + kb + lc * 8;   \
        const __nv_bfloat16* b1p = g_Wh + (size_t)(n0 + lr + 64) * KP_ + kb + lc * 8; \
        const __nv_bfloat16* e0p = g_Wl + (size_t)(n0 + lr) * KP_ + kb + lc * 8;   \
        const __nv_bfloat16* e1p = g_Wl + (size_t)(n0 + lr + 64) * KP_ + kb + lc * 8; \
        cpa16(st0, a0p);               cpa16(st1, a1p);                            \
        cpa16(st0 + MAT_B, c0p);       cpa16(st1 + MAT_B, c1p);                    \
        cpa16(st0 + 2 * MAT_B, b0p);   cpa16(st1 + 2 * MAT_B, b1p);                \
        cpa16(st0 + 3 * MAT_B, e0p);   cpa16(st1 + 3 * MAT_B, e1p);                \
    } while (0)

    ISSUE(0, 0);
    asm volatile("cp.async.commit_group;" ::: "memory");
    ISSUE(1, 1);
    asm volatile("cp.async.commit_group;" ::: "memory");
    asm volatile("cp.async.wait_group 1;" ::: "memory");
    __syncthreads();

    int wm = (wid >> 1) * 32, wn = (wid & 1) * 64;
    uint32_t aoff = (uint32_t)(wm + (lid & 15)) * ASTRIDE + (lid >> 4) * 16;
    uint32_t boff = (uint32_t)(wn + (lid & 7) + ((lid >> 4) & 1) * 8) * ASTRIDE
                  + ((lid >> 3) & 1) * 16 + 2 * MAT_B;

    for (int kc = 0; kc < NT_; kc++) {
        uint32_t st = sb + (kc & 1) * STG_B;
#pragma unroll
        for (int ks = 0; ks < 2; ks++) {
            uint32_t ah[2][4], al[2][4];
#pragma unroll
            for (int mm = 0; mm < 2; mm++) {
                uint32_t ad = st + aoff + mm * (16 * ASTRIDE) + ks * 32;
                LDMX4(ah[mm], ad);
                LDMX4(al[mm], ad + MAT_B);
            }
#pragma unroll
            for (int nt = 0; nt < 4; nt++) {
                uint32_t bh[4], bl[4];
                uint32_t bd = st + boff + nt * (16 * ASTRIDE) + ks * 32;
                LDMX4(bh, bd);
                LDMX4(bl, bd + MAT_B);
#pragma unroll
                for (int mm = 0; mm < 2; mm++) {
                    MMA(acc[mm][nt * 2],     ah[mm], bh[0], bh[1]);
                    MMA(acc[mm][nt * 2 + 1], ah[mm], bh[2], bh[3]);
                    MMA(acc[mm][nt * 2],     al[mm], bh[0], bh[1]);
                    MMA(acc[mm][nt * 2 + 1], al[mm], bh[2], bh[3]);
                    MMA(acc[mm][nt * 2],     ah[mm], bl[0], bl[1]);
                    MMA(acc[mm][nt * 2 + 1], ah[mm], bl[2], bl[3]);
                }
            }
        }
        __syncthreads();
        if (kc + 2 < NT_) ISSUE(kc + 2, kc & 1);
        asm volatile("cp.async.commit_group;" ::: "memory");
        asm volatile("cp.async.wait_group 1;" ::: "memory");
        __syncthreads();
    }

    // epilogue: out[m][n] = acc + bias, scattered to outputs[b, kstep+1, :]
#pragma unroll
    for (int mm = 0; mm < 2; mm++)
#pragma unroll
        for (int i = 0; i < 2; i++) {
            int m = m0 + wm + mm * 16 + (lid >> 2) + i * 8;
            if (m < MX_) {
                int kstep = m >> 5, b = m & 31;
                float* orow = out + (size_t)(b * T_ + kstep + 1) * V_;
#pragma unroll
                for (int nn = 0; nn < 8; nn++) {
                    int n = n0 + wn + nn * 8 + (lid & 3) * 2;
                    float2 bs = *reinterpret_cast<const float2*>(&fcb[n]);
                    float2 o;
                    o.x = acc[mm][nn][i * 2]     + bs.x;
                    o.y = acc[mm][nn][i * 2 + 1] + bs.y;
                    *reinterpret_cast<float2*>(&orow[n]) = o;
                }
            }
        }
}

// ---------------- argmax with exact fp32 fixup for near-ties ----------------
__global__ void k_argmax(const float* __restrict__ out, const float* __restrict__ fcW,
                         const float* __restrict__ fcb, float* __restrict__ tok) {
    int r = blockIdx.x;               // r = b*96 + t
    int b = r / T_, t = r % T_;
    const float* row = out + (size_t)r * V_;
    int tid = threadIdx.x;
    float best = -__int_as_float(0x7f800000);
    int bi = 0;
    for (int v = tid; v < V_; v += 256) {
        float f = row[v];
        if (f > best) { best = f; bi = v; }
    }
    __shared__ float bv[256];
    __shared__ int bid[256];
    bv[tid] = best; bid[tid] = bi; __syncthreads();
    for (int off = 128; off > 0; off >>= 1) {
        if (tid < off) {
            if (bv[tid + off] > bv[tid] ||
                (bv[tid + off] == bv[tid] && bid[tid + off] < bid[tid])) {
                bv[tid] = bv[tid + off]; bid[tid] = bid[tid + off];
            }
        }
        __syncthreads();
    }
    float bestv = bv[0];
    int   besti = bid[0];
    __syncthreads();

    // gather candidates within eps of max; if ambiguous, recompute exact fp32 dots
    __shared__ int cand[8];
    __shared__ int ncand;
    if (tid == 0) ncand = 0;
    __syncthreads();
    const float eps = 1e-4f;
    for (int v = tid; v < V_; v += 256) {
        if (row[v] >= bestv - eps) {
            int p = atomicAdd(&ncand, 1);
            if (p < 8) cand[p] = v;
        }
    }
    __syncthreads();
    int nc = ncand;
    if (t == 0 || nc <= 1 || nc > 8) {
        if (tid == 0) tok[r] = (float)besti;
        return;
    }
    int m = (t - 1) * B_ + b;
    const float* x = g_X + (size_t)m * KX_;
    float bvv = -__int_as_float(0x7f800000);
    int   bii = 0x7fffffff;
    for (int ci = 0; ci < nc; ci++) {
        int n = cand[ci];
        const float* w = fcW + (size_t)n * KX_;
        float p = 0.0f;
        for (int q = tid; q < KX_; q += 256) p = fmaf(x[q], w[q], p);
        bv[tid] = p; __syncthreads();
        for (int off = 128; off > 0; off >>= 1) {
            if (tid < off) bv[tid] += bv[tid + off];
            __syncthreads();
        }
        float val = bv[0] + fcb[n];
        if (val > bvv || (val == bvv && n < bii)) { bvv = val; bii = n; }
        __syncthreads();
    }
    if (tid == 0) tok[r] = (float)bii;
}

// ---------------- launch ----------------
extern "C" void kernel_launch(void* const* d_in, const int* in_sizes, int n_in,
                              void* d_out, int out_size) {
    const float* enc    = (const float*)d_in[0];
    const int*   trg    = (const int*)  d_in[1];
    const float* emb    = (const float*)d_in[2];
    const float* attn_W = (const float*)d_in[3];
    const float* attn_b = (const float*)d_in[4];
    const float* attn_v = (const float*)d_in[5];
    const float* W_ih   = (const float*)d_in[6];
    const float* W_hh   = (const float*)d_in[7];
    const float* b_ih   = (const float*)d_in[8];
    const float* b_hh   = (const float*)d_in[9];
    const float* fc_W   = (const float*)d_in[10];
    const float* fc_b   = (const float*)d_in[11];
    float* out = (float*)d_out;

    cudaFuncSetAttribute(k_fc_mma, cudaFuncAttributeMaxDynamicSharedMemorySize, 2 * STG_B);

    k_zero_t0<<<B_, 256>>>(out);
    k_embed<<<dim3(NS_, B_), 256>>>(trg, emb);
    k_cvtW<<<V_, 128>>>(fc_W);
    k_encproj<<<(B_ * S_) / 64, 256>>>(enc, attn_W, attn_b);

    for (int k = 0; k < NS_; k++) {
        k_attn<<<B_ * 8, 128>>>(k, attn_W, attn_v);
        k_softw<<<dim3(B_, 3), 256>>>(k, enc);
        k_gates<<<64, 256>>>(k, W_ih, W_hh, b_ih, b_hh);
    }
    k_final_cell<<<B_, 128>>>();
    k_cvtX<<<MP_, 128>>>();

    k_fc_mma<<<dim3(MP_ / 128, V_ / 128), 256, 2 * STG_B>>>(fc_b, out);

    const long long btv = (long long)B_ * T_ * V_;
    if ((long long)out_size >= btv + (long long)B_ * T_) {
        k_argmax<<<B_ * T_, 256>>>(out, fc_W, fc_b, out + btv);
    }
}